// round 14
// baseline (speedup 1.0000x reference)
#include <cuda_runtime.h>
#include <cuda_bf16.h>
#include <cstdint>

// data:  [B, C, N] fp32;  edges: [E, 2] int32
// out:   [B, C, N+E] fp32; head N cols zero, col N+e = (d[p0]+d[p1])*0.5
static constexpr int B_    = 4;
static constexpr int C_    = 128;
static constexpr int N_    = 100000;
static constexpr int E_    = 200000;
static constexpr int BC_   = B_ * C_;    // 512
static constexpr int M_    = N_ + E_;    // 300000
static constexpr int N4_   = N_ / 4;     // 25000
static constexpr int M4_   = M_ / 4;     // 75000

static constexpr int BCP_   = 64;        // bc channels per pass
static constexpr int BCP4_  = BCP_ / 4;  // 16
static constexpr int NPASS  = BC_ / BCP_;// 8
static constexpr int TILE_E = 128;       // edges per gather tile
static constexpr int NGTILE = (E_ + TILE_E - 1) / TILE_E;  // 1563 (last: 64)
static constexpr int TILE_N = 32;
static constexpr int NTTILE = N_ / TILE_N;                 // 3125

static constexpr int NCTAS  = 576;       // < 148*4: guaranteed co-resident

// Double-buffered transposed slice [N][64] fp32, 25.6 MB each (51.2 MB total
// proven L2-resident in earlier rounds).
__device__ float g_scratch[2][(size_t)N_ * BCP_];
// Monotonic ticket-barrier counters (replay-safe: never reset).
__device__ unsigned g_bar[16];

static constexpr int SMEM_BYTES = TILE_E * BCP_ * 4 + TILE_E * 2 * 4; // 33 KB

// ---------------------------------------------------------------------------
// Grid-wide ticket barrier. Requires all NCTAS CTAs co-resident.
// Monotonic counter: epoch = my/NCTAS, works across CUDA-graph replays.
// ---------------------------------------------------------------------------
__device__ __forceinline__ void grid_barrier(int p) {
    __syncthreads();
    if (threadIdx.x == 0) {
        __threadfence();                                  // release
        const unsigned my = atomicAdd(&g_bar[p], 1u);
        const unsigned target = (my / NCTAS + 1u) * NCTAS;
        unsigned v;
        do {
            asm volatile("ld.acquire.gpu.u32 %0, [%1];"
                         : "=r"(v) : "l"(&g_bar[p]));
            if (v >= target) break;
            __nanosleep(100);
        } while (true);
    }
    __syncthreads();
}

// ---------------------------------------------------------------------------
// Transpose role: data[bc0..bc0+63][n0..n0+31] -> buf[n][64]. 512 threads.
// ---------------------------------------------------------------------------
__device__ __forceinline__
void transpose_role(const float* __restrict__ data, float* __restrict__ buf,
                    int bc0, int tileIdx, char* smem) {
    float (*tile)[33] = reinterpret_cast<float (*)[33]>(smem);   // [64][33]
    const int t    = threadIdx.x;
    const int lane = t & 31;
    const int w    = t >> 5;
    const int n0   = tileIdx * TILE_N;

    #pragma unroll
    for (int k = 0; k < 4; ++k) {
        const int row = k * 16 + w;                 // bc within slice
        tile[row][lane] = __ldcs(&data[(size_t)(bc0 + row) * N_ + n0 + lane]);
    }
    __syncthreads();

    const int nl = t >> 4;                          // 0..31
    const int c4 = t & 15;                          // bc float4 0..15
    float4 v;
    v.x = tile[4 * c4 + 0][nl];
    v.y = tile[4 * c4 + 1][nl];
    v.z = tile[4 * c4 + 2][nl];
    v.w = tile[4 * c4 + 3][nl];
    reinterpret_cast<float4*>(buf)[(size_t)(n0 + nl) * BCP4_ + c4] = v;
    __syncthreads();                                // smem reuse across tiles
}

// ---------------------------------------------------------------------------
// Gather role: zero-head chunk + up to 128-edge tile for one 64-bc slice.
// SMEM mid (el, bc): word = el*64 + 4*((bc>>2) ^ ((el>>2)&15)) + (bc&3).
// ---------------------------------------------------------------------------
__device__ __forceinline__
void gather_role(const int* __restrict__ edges, float* __restrict__ out,
                 const float* __restrict__ buf, int bc0, int tileIdx,
                 char* smem) {
    float* mid   = reinterpret_cast<float*>(smem);
    int*   sedge = reinterpret_cast<int*>(smem + TILE_E * BCP_ * 4);

    const int t  = threadIdx.x;
    const int e0 = tileIdx * TILE_E;
    const int nE = (E_ - e0 < TILE_E) ? (E_ - e0) : TILE_E;

    // fused zero head: 64 rows * 25000 float4 spread over the 1563 tiles
    {
        const float4 z = make_float4(0.f, 0.f, 0.f, 0.f);
        float4* __restrict__ o4 = reinterpret_cast<float4*>(out);
        #pragma unroll
        for (int k = 0; k < 2; ++k) {
            const int idx = tileIdx * 1024 + k * 512 + t;
            if (idx < BCP_ * N4_) {
                const int bcl = idx / N4_;
                const int j4  = idx - bcl * N4_;
                __stcs(&o4[(size_t)(bc0 + bcl) * M4_ + j4], z);
            }
        }
    }

    if (t < 2 * nE) sedge[t] = __ldg(&edges[e0 * 2 + t]);
    __syncthreads();

    // phase A: float4 gather-average from L2-resident scratch
    const int q = t >> 4;                           // edge slot 0..31
    const int m = t & 15;                           // bc float4 0..15
    const float4* __restrict__ dT4 = reinterpret_cast<const float4*>(buf);
    float4* __restrict__ mid4 = reinterpret_cast<float4*>(mid);

    #pragma unroll
    for (int it = 0; it < 4; ++it) {
        const int el = it * 32 + q;
        if (el < nE) {
            const int p0 = sedge[2 * el];
            const int p1 = sedge[2 * el + 1];
            const float4 a = __ldg(&dT4[(size_t)p0 * BCP4_ + m]);
            const float4 b = __ldg(&dT4[(size_t)p1 * BCP4_ + m]);
            float4 r;
            r.x = (a.x + b.x) * 0.5f;
            r.y = (a.y + b.y) * 0.5f;
            r.z = (a.z + b.z) * 0.5f;
            r.w = (a.w + b.w) * 0.5f;
            mid4[el * BCP4_ + (m ^ ((el >> 2) & 15))] = r;
        }
    }
    __syncthreads();

    // phase B: transpose-on-write, 128B coalesced streaming stores
    const int w   = t >> 5;
    const int l   = t & 31;
    const int j   = l & 7;
    const int bcl = w * 4 + (l >> 3);               // 0..63
    const int g4  = bcl >> 2;
    const int b3  = bcl & 3;
    float4* __restrict__ dst =
        reinterpret_cast<float4*>(out + (size_t)(bc0 + bcl) * M_);
    #pragma unroll
    for (int h = 0; h < 4; ++h) {
        const int jj = j + 8 * h;                   // float4 span 0..31
        if (jj * 4 < nE) {
            float4 r;
            r.x = mid[(4 * jj + 0) * BCP_ + 4 * (g4 ^ (jj & 15)) + b3];
            r.y = mid[(4 * jj + 1) * BCP_ + 4 * (g4 ^ (jj & 15)) + b3];
            r.z = mid[(4 * jj + 2) * BCP_ + 4 * (g4 ^ (jj & 15)) + b3];
            r.w = mid[(4 * jj + 3) * BCP_ + 4 * (g4 ^ (jj & 15)) + b3];
            __stcs(&dst[N4_ + (e0 >> 2) + jj], r);
        }
    }
    __syncthreads();                                // smem reuse across tiles
}

// ---------------------------------------------------------------------------
// Persistent pipelined kernel: all 8 passes in one launch, grid barriers
// between phases. Phase p: gather slice p (from buf p&1) + transpose slice
// p+1 (into buf (p+1)&1), tiles interleaved across CTAs for balance.
// ---------------------------------------------------------------------------
__global__ __launch_bounds__(512, 4)
void persistent_kernel(const float* __restrict__ data,
                       const int*   __restrict__ edges,
                       float*       __restrict__ out) {
    __shared__ __align__(16) char smem[SMEM_BYTES];

    // Prologue phase: transpose slice 0 -> buf 0
    for (int idx = blockIdx.x; idx < NTTILE; idx += NCTAS)
        transpose_role(data, g_scratch[0], 0, idx, smem);
    grid_barrier(0);

    for (int p = 0; p < NPASS; ++p) {
        const int nT = (p + 1 < NPASS) ? NTTILE : 0;
        for (int idx = blockIdx.x; idx < NGTILE + nT; idx += NCTAS) {
            if (idx < NGTILE)
                gather_role(edges, out, g_scratch[p & 1], p * BCP_, idx, smem);
            else
                transpose_role(data, g_scratch[(p + 1) & 1],
                               (p + 1) * BCP_, idx - NGTILE, smem);
        }
        if (p + 1 < NPASS) grid_barrier(p + 1);
    }
}

extern "C" void kernel_launch(void* const* d_in, const int* in_sizes, int n_in,
                              void* d_out, int out_size) {
    const float* data  = (const float*)d_in[0];
    const int*   edges = (const int*)d_in[1];
    float*       out   = (float*)d_out;

    persistent_kernel<<<NCTAS, 512>>>(data, edges, out);
}